// round 7
// baseline (speedup 1.0000x reference)
#include <cuda_runtime.h>

#define NB   4
#define NP   4096
#define TILE 128
#define RT   8
#define CT   8
#define NMIN (2 * NB * NP)                       // 32768 mins: [gt | coord]
#define NBLK (NB * (NP / TILE) * (NP / TILE))    // 4096 blocks

typedef unsigned long long ull;

// Scratch, zero-initialized at module load. Keys are ~float_bits(d) so the
// atomicMax identity is 0 — no init kernel needed. The last block resets
// everything to 0 so every graph replay starts clean.
__device__ unsigned g_key[NMIN];
__device__ unsigned g_count = 0;

// ---- packed f32x2 helpers (sm_103a) ----
__device__ __forceinline__ ull pk2(float lo, float hi) {
    ull r; asm("mov.b64 %0, {%1,%2};" : "=l"(r) : "f"(lo), "f"(hi)); return r;
}
__device__ __forceinline__ void upk2(float& lo, float& hi, ull v) {
    asm("mov.b64 {%0,%1}, %2;" : "=f"(lo), "=f"(hi) : "l"(v));
}
__device__ __forceinline__ ull fma2(ull a, ull b, ull c) {
    ull d; asm("fma.rn.f32x2 %0, %1, %2, %3;" : "=l"(d) : "l"(a), "l"(b), "l"(c)); return d;
}
__device__ __forceinline__ ull add2(ull a, ull b) {
    ull d; asm("add.rn.f32x2 %0, %1, %2;" : "=l"(d) : "l"(a), "l"(b)); return d;
}

__global__ __launch_bounds__(256) void chamfer_fused_kernel(
    const float* __restrict__ coord, const float* __restrict__ gt,
    float* __restrict__ out)
{
    __shared__ __align__(16) float sgx[TILE], sgy[TILE], sgz[TILE];
    __shared__ __align__(16) float scx2[TILE], scy2[TILE], scz2[TILE], scn[TILE];
    __shared__ unsigned srowkey[TILE];
    __shared__ unsigned scolkey[TILE];
    __shared__ float red[8];
    __shared__ int is_last;

    const int b    = blockIdx.z;
    const int row0 = blockIdx.y * TILE;   // gt rows
    const int col0 = blockIdx.x * TILE;   // coord cols
    const int t    = threadIdx.x;

    // Stage tiles. Coord side pre-transformed: (-2x,-2y,-2z, |c|^2).
    if (t < TILE) {
        const float* p = gt + (size_t)(b * NP + row0 + t) * 3;
        sgx[t] = p[0]; sgy[t] = p[1]; sgz[t] = p[2];
        scolkey[t] = 0u;
    } else {
        const int u = t - TILE;
        const float* p = coord + (size_t)(b * NP + col0 + u) * 3;
        const float x = p[0], y = p[1], z = p[2];
        scx2[u] = -2.0f * x; scy2[u] = -2.0f * y; scz2[u] = -2.0f * z;
        scn[u]  = fmaf(x, x, fmaf(y, y, z * z));
    }
    __syncthreads();

    const int ty = t >> 4;
    const int tx = t & 15;

    float rx[RT], ry[RT], rz[RT], rn[RT];
#pragma unroll
    for (int i = 0; i < RT; i++) {
        const int r = ty * RT + i;
        rx[i] = sgx[r]; ry[i] = sgy[r]; rz[i] = sgz[r];
        rn[i] = fmaf(rx[i], rx[i], fmaf(ry[i], ry[i], rz[i] * rz[i]));
    }

    // Column side as f32x2 packs (4 packs of 2 columns).
    ull cX[CT/2], cY[CT/2], cZ[CT/2], cB[CT/2];
    {
        const float2* px = (const float2*)&scx2[tx * CT];
        const float2* py = (const float2*)&scy2[tx * CT];
        const float2* pz = (const float2*)&scz2[tx * CT];
        const float2* pn = (const float2*)&scn [tx * CT];
#pragma unroll
        for (int jp = 0; jp < CT/2; jp++) {
            float2 vx = px[jp], vy = py[jp], vz = pz[jp], vn = pn[jp];
            cX[jp] = pk2(vx.x, vx.y);
            cY[jp] = pk2(vy.x, vy.y);
            cZ[jp] = pk2(vz.x, vz.y);
            cB[jp] = pk2(vn.x, vn.y);
        }
    }

    const float INF = __int_as_float(0x7F800000);
    float rmin[RT], cmin[CT];
#pragma unroll
    for (int i = 0; i < RT; i++) rmin[i] = INF;
#pragma unroll
    for (int j = 0; j < CT; j++) cmin[j] = INF;

    // d = (rn + cn) + rx*(-2cx) + ry*(-2cy) + rz*(-2cz)
    // Per packed pair: 1 add.f32x2 + 3 fma.f32x2 (fma pipe) + 4 FMNMX (alu pipe).
#pragma unroll
    for (int i = 0; i < RT; i++) {
        const ull rX = pk2(rx[i], rx[i]);
        const ull rY = pk2(ry[i], ry[i]);
        const ull rZ = pk2(rz[i], rz[i]);
        const ull rN = pk2(rn[i], rn[i]);
#pragma unroll
        for (int jp = 0; jp < CT/2; jp++) {
            ull acc = add2(cB[jp], rN);
            acc = fma2(rX, cX[jp], acc);
            acc = fma2(rY, cY[jp], acc);
            acc = fma2(rZ, cZ[jp], acc);
            float lo, hi; upk2(lo, hi, acc);
            rmin[i]        = fminf(rmin[i], fminf(lo, hi));
            cmin[2*jp]     = fminf(cmin[2*jp], lo);
            cmin[2*jp + 1] = fminf(cmin[2*jp + 1], hi);
        }
    }

    // Row mins across tx (16 lanes within warp half), publish keys.
#pragma unroll
    for (int i = 0; i < RT; i++) {
        float v = rmin[i];
        v = fminf(v, __shfl_xor_sync(0xFFFFFFFFu, v, 1));
        v = fminf(v, __shfl_xor_sync(0xFFFFFFFFu, v, 2));
        v = fminf(v, __shfl_xor_sync(0xFFFFFFFFu, v, 4));
        v = fminf(v, __shfl_xor_sync(0xFFFFFFFFu, v, 8));
        rmin[i] = v;
    }
    if (tx == 0) {
#pragma unroll
        for (int i = 0; i < RT; i++)
            srowkey[ty * RT + i] = ~__float_as_uint(fmaxf(rmin[i], 0.0f));
    }

    // Col mins: fold the warp's two ty, then shared atomicMax across warps.
#pragma unroll
    for (int j = 0; j < CT; j++)
        cmin[j] = fminf(cmin[j], __shfl_xor_sync(0xFFFFFFFFu, cmin[j], 16));
    if ((t & 16) == 0) {
#pragma unroll
        for (int j = 0; j < CT; j++)
            atomicMax(&scolkey[tx * CT + j], ~__float_as_uint(fmaxf(cmin[j], 0.0f)));
    }
    __syncthreads();

    // Publish partial mins to global scratch (max on inverted bits == float min).
    if (t < TILE) {
        atomicMax(&g_key[b * NP + row0 + t], srowkey[t]);
    } else {
        const int u = t - TILE;
        atomicMax(&g_key[NB * NP + b * NP + col0 + u], scolkey[u]);
    }

    // ---- last-block fused reduction ----
    __threadfence();
    __syncthreads();
    if (t == 0) {
        unsigned ticket = atomicAdd(&g_count, 1u);
        is_last = (ticket == (unsigned)(NBLK - 1));
    }
    __syncthreads();
    if (!is_last) return;

    // All prior blocks' atomics are visible (fence + ticket). Sum and reset.
    float s = 0.0f;
    const uint4* pk = (const uint4*)g_key;
    uint4* pw = (uint4*)g_key;
    const uint4 zero4 = make_uint4(0u, 0u, 0u, 0u);
    for (int i = t; i < NMIN / 4; i += 256) {
        uint4 v = __ldcg(&pk[i]);
        s += __uint_as_float(~v.x) + __uint_as_float(~v.y)
           + __uint_as_float(~v.z) + __uint_as_float(~v.w);
        pw[i] = zero4;
    }
#pragma unroll
    for (int m = 16; m; m >>= 1)
        s += __shfl_xor_sync(0xFFFFFFFFu, s, m);
    if ((t & 31) == 0) red[t >> 5] = s;
    __syncthreads();
    if (t == 0) {
        float total = 0.0f;
#pragma unroll
        for (int w = 0; w < 8; w++) total += red[w];
        out[0] = total * (1.0f / (float)(NB * NP));
        g_count = 0u;   // reset for next graph replay
    }
}

extern "C" void kernel_launch(void* const* d_in, const int* in_sizes, int n_in,
                              void* d_out, int out_size) {
    (void)in_sizes; (void)n_in; (void)out_size;
    const float* coord = (const float*)d_in[0];  // [B, N, 3]
    const float* gt    = (const float*)d_in[1];  // [B, M, 3]
    dim3 grid(NP / TILE, NP / TILE, NB);         // (32, 32, 4) = 4096 blocks
    chamfer_fused_kernel<<<grid, 256>>>(coord, gt, (float*)d_out);
}

// round 9
// speedup vs baseline: 1.1651x; 1.1651x over previous
#include <cuda_runtime.h>

#define NB   4
#define NP   4096
#define TILE 128
#define RT   8
#define CT   8
#define NMIN (2 * NB * NP)                       // 32768 mins: [gt | coord]
#define NBLK (NB * (NP / TILE) * (NP / TILE))    // 4096 blocks

// Scratch, zero-initialized at module load. Keys are ~float_bits(d) so the
// atomicMax identity is 0 — no init kernel needed. The last block resets
// everything to 0 so every graph replay starts clean.
__device__ unsigned g_key[NMIN];
__device__ unsigned g_count = 0;

__global__ __launch_bounds__(256) void chamfer_fused_kernel(
    const float* __restrict__ coord, const float* __restrict__ gt,
    float* __restrict__ out)
{
    __shared__ float sgx[TILE], sgy[TILE], sgz[TILE], sgn[TILE];
    __shared__ float scx2[TILE], scy2[TILE], scz2[TILE], scn[TILE];
    __shared__ unsigned srowkey[TILE];
    __shared__ unsigned scolkey[TILE];
    __shared__ float red[8];
    __shared__ int is_last;

    const int b    = blockIdx.z;
    const int row0 = blockIdx.y * TILE;   // gt rows
    const int col0 = blockIdx.x * TILE;   // coord cols
    const int t    = threadIdx.x;

    // Stage tiles. Coord side pre-transformed: (-2x,-2y,-2z, |c|^2).
    if (t < TILE) {
        const float* p = gt + (size_t)(b * NP + row0 + t) * 3;
        const float x = p[0], y = p[1], z = p[2];
        sgx[t] = x; sgy[t] = y; sgz[t] = z;
        sgn[t] = fmaf(x, x, fmaf(y, y, z * z));
        scolkey[t] = 0u;
    } else {
        const int u = t - TILE;
        const float* p = coord + (size_t)(b * NP + col0 + u) * 3;
        const float x = p[0], y = p[1], z = p[2];
        scx2[u] = -2.0f * x; scy2[u] = -2.0f * y; scz2[u] = -2.0f * z;
        scn[u]  = fmaf(x, x, fmaf(y, y, z * z));
    }
    __syncthreads();

    const int ty = t >> 4;
    const int tx = t & 15;

    float rx[RT], ry[RT], rz[RT], rn[RT];
#pragma unroll
    for (int i = 0; i < RT; i++) {
        const int r = ty * RT + i;
        rx[i] = sgx[r]; ry[i] = sgy[r]; rz[i] = sgz[r]; rn[i] = sgn[r];
    }
    float cx[CT], cy[CT], cz[CT], cn[CT];
#pragma unroll
    for (int j = 0; j < CT; j++) {
        const int c = tx * CT + j;
        cx[j] = scx2[c]; cy[j] = scy2[c]; cz[j] = scz2[c]; cn[j] = scn[c];
    }

    const float INF = __int_as_float(0x7F800000);
    float rmin[RT], cmin[CT];
#pragma unroll
    for (int i = 0; i < RT; i++) rmin[i] = INF;
#pragma unroll
    for (int j = 0; j < CT; j++) cmin[j] = INF;

    // d = (rn + cn) + rx*(-2cx) + ry*(-2cy) + rz*(-2cz)
    // Per distance: 1 FADD + 3 FFMA (fma pipe) + 2 FMNMX (alu pipe).
#pragma unroll
    for (int i = 0; i < RT; i++) {
#pragma unroll
        for (int j = 0; j < CT; j++) {
            float d = rn[i] + cn[j];
            d = fmaf(rx[i], cx[j], d);
            d = fmaf(ry[i], cy[j], d);
            d = fmaf(rz[i], cz[j], d);
            rmin[i] = fminf(rmin[i], d);
            cmin[j] = fminf(cmin[j], d);
        }
    }

    // Row mins across tx (16 lanes within the warp half), publish keys.
#pragma unroll
    for (int i = 0; i < RT; i++) {
        float v = rmin[i];
        v = fminf(v, __shfl_xor_sync(0xFFFFFFFFu, v, 1));
        v = fminf(v, __shfl_xor_sync(0xFFFFFFFFu, v, 2));
        v = fminf(v, __shfl_xor_sync(0xFFFFFFFFu, v, 4));
        v = fminf(v, __shfl_xor_sync(0xFFFFFFFFu, v, 8));
        rmin[i] = v;
    }
    if (tx == 0) {
#pragma unroll
        for (int i = 0; i < RT; i++)
            srowkey[ty * RT + i] = ~__float_as_uint(fmaxf(rmin[i], 0.0f));
    }

    // Col mins: fold the warp's two ty, then shared atomicMax across warps.
#pragma unroll
    for (int j = 0; j < CT; j++)
        cmin[j] = fminf(cmin[j], __shfl_xor_sync(0xFFFFFFFFu, cmin[j], 16));
    if ((t & 16) == 0) {
#pragma unroll
        for (int j = 0; j < CT; j++)
            atomicMax(&scolkey[tx * CT + j], ~__float_as_uint(fmaxf(cmin[j], 0.0f)));
    }
    __syncthreads();

    // Publish partial mins to global scratch (max on inverted bits == float min).
    if (t < TILE) {
        atomicMax(&g_key[b * NP + row0 + t], srowkey[t]);
    } else {
        const int u = t - TILE;
        atomicMax(&g_key[NB * NP + b * NP + col0 + u], scolkey[u]);
    }

    // ---- last-block fused reduction ----
    __threadfence();
    __syncthreads();
    if (t == 0) {
        unsigned ticket = atomicAdd(&g_count, 1u);
        is_last = (ticket == (unsigned)(NBLK - 1));
    }
    __syncthreads();
    if (!is_last) return;

    // All prior blocks' atomics are visible (fence + ticket). Sum and reset.
    float s = 0.0f;
    const uint4* pk = (const uint4*)g_key;
    uint4* pw = (uint4*)g_key;
    const uint4 zero4 = make_uint4(0u, 0u, 0u, 0u);
    for (int i = t; i < NMIN / 4; i += 256) {
        uint4 v = __ldcg(&pk[i]);
        s += __uint_as_float(~v.x) + __uint_as_float(~v.y)
           + __uint_as_float(~v.z) + __uint_as_float(~v.w);
        pw[i] = zero4;
    }
#pragma unroll
    for (int m = 16; m; m >>= 1)
        s += __shfl_xor_sync(0xFFFFFFFFu, s, m);
    if ((t & 31) == 0) red[t >> 5] = s;
    __syncthreads();
    if (t == 0) {
        float total = 0.0f;
#pragma unroll
        for (int w = 0; w < 8; w++) total += red[w];
        out[0] = total * (1.0f / (float)(NB * NP));
        g_count = 0u;   // reset for next graph replay
    }
}

extern "C" void kernel_launch(void* const* d_in, const int* in_sizes, int n_in,
                              void* d_out, int out_size) {
    (void)in_sizes; (void)n_in; (void)out_size;
    const float* coord = (const float*)d_in[0];  // [B, N, 3]
    const float* gt    = (const float*)d_in[1];  // [B, M, 3]
    dim3 grid(NP / TILE, NP / TILE, NB);         // (32, 32, 4) = 4096 blocks
    chamfer_fused_kernel<<<grid, 256>>>(coord, gt, (float*)d_out);
}